// round 13
// baseline (speedup 1.0000x reference)
#include <cuda_runtime.h>
#include <math.h>

#define BB 8
#define SS 1024
#define DD 512
#define HH 9
#define DHH 64
#define HD (HH*DHH)          // 576
#define INV_SCALE 0.13258252147247766f   // 1/sqrt(512/9)
#define LN_EPS 1e-5f

// ---------------- scratch (no allocs allowed) ----------------
__device__ float g_q[BB*HH*SS*DHH];   // [BH, S, DH]
__device__ float g_k[BB*HH*SS*DHH];
__device__ float g_v[BB*HH*SS*DHH];
__device__ float g_ctx[BB*SS*HD];     // [B*S, H*DH]
__device__ float g_x[BB*SS*DD];       // pre-LN activations

// ---------------- mma helper (raw fp32 bits as tf32: RZ truncation) ----------------
__device__ __forceinline__ void mma_tf32(float c[4],
                                         unsigned a0, unsigned a1, unsigned a2, unsigned a3,
                                         unsigned b0, unsigned b1)
{
    asm volatile(
        "mma.sync.aligned.m16n8k8.row.col.f32.tf32.tf32.f32 "
        "{%0,%1,%2,%3}, {%4,%5,%6,%7}, {%8,%9}, {%0,%1,%2,%3};\n"
        : "+f"(c[0]), "+f"(c[1]), "+f"(c[2]), "+f"(c[3])
        : "r"(a0), "r"(a1), "r"(a2), "r"(a3), "r"(b0), "r"(b1));
}

__device__ __forceinline__ void ldsm4(unsigned& r0, unsigned& r1, unsigned& r2, unsigned& r3,
                                      unsigned addr)
{
    asm volatile("ldmatrix.sync.aligned.m8n8.x4.shared.b16 {%0,%1,%2,%3}, [%4];\n"
                 : "=r"(r0), "=r"(r1), "=r"(r2), "=r"(r3) : "r"(addr));
}

#define CP_ASYNC16(dst_u32, src_ptr) \
    asm volatile("cp.async.ca.shared.global [%0], [%1], 16;\n" :: "r"(dst_u32), "l"(src_ptr))
#define CP_COMMIT() asm volatile("cp.async.commit_group;\n" ::)
#define CP_WAIT1()  asm volatile("cp.async.wait_group 1;\n" ::)
#define CP_WAIT0()  asm volatile("cp.async.wait_group 0;\n" ::)

// ---------------- K1: QKV projection, 64x192 tiles ----------------
#define QKV_N 192
#define QKV_BSTR 196
__global__ __launch_bounds__(256) void qkv_mma(
    const float* __restrict__ Xq, const float* __restrict__ Xk, const float* __restrict__ Xv,
    const float* __restrict__ Wq, const float* __restrict__ bq,
    const float* __restrict__ Wk, const float* __restrict__ bk,
    const float* __restrict__ Wv, const float* __restrict__ bv)
{
    const int which = blockIdx.z;
    const float* X = (which == 0) ? Xq : (which == 1) ? Xk : Xv;
    const float* W = (which == 0) ? Wq : (which == 1) ? Wk : Wv;
    const float* bias = (which == 0) ? bq : (which == 1) ? bk : bv;
    float* out = (which == 0) ? g_q : (which == 1) ? g_k : g_v;

    __shared__ float As[64 * 36];
    __shared__ float Bs[32 * QKV_BSTR];

    const int tid = threadIdx.x;
    const int w = tid >> 5, lane = tid & 31, g = lane >> 2, t = lane & 3;
    const int mw = w & 1;
    const int nw = w >> 1;
    const int row0 = blockIdx.y * 64;
    const int col0 = blockIdx.x * QKV_N;

    float acc[12][4] = {};

    for (int k0 = 0; k0 < DD; k0 += 32) {
        __syncthreads();
        #pragma unroll
        for (int j = 0; j < 2; j++) {
            int f = tid + j * 256;
            int r = f >> 3, c4 = (f & 7) * 4;
            *(float4*)&As[r * 36 + c4] = *(const float4*)&X[(size_t)(row0 + r) * DD + k0 + c4];
        }
        #pragma unroll
        for (int j = 0; j < 6; j++) {
            int f = tid + j * 256;
            int r = f / 48, c4 = (f % 48) * 4;
            *(float4*)&Bs[r * QKV_BSTR + c4] =
                *(const float4*)&W[(size_t)(k0 + r) * HD + col0 + c4];
        }
        __syncthreads();
        #pragma unroll
        for (int kk = 0; kk < 4; kk++) {
            unsigned a[2][4];
            #pragma unroll
            for (int mi = 0; mi < 2; mi++) {
                const float* ap = As + (mw * 32 + mi * 16 + g) * 36 + kk * 8 + t;
                a[mi][0] = __float_as_uint(ap[0]);
                a[mi][1] = __float_as_uint(ap[8 * 36]);
                a[mi][2] = __float_as_uint(ap[4]);
                a[mi][3] = __float_as_uint(ap[8 * 36 + 4]);
            }
            #pragma unroll
            for (int nb = 0; nb < 6; nb++) {
                int nc = nw * 48 + nb * 8 + g;
                unsigned b0 = __float_as_uint(Bs[(kk * 8 + t) * QKV_BSTR + nc]);
                unsigned b1 = __float_as_uint(Bs[(kk * 8 + t + 4) * QKV_BSTR + nc]);
                mma_tf32(acc[nb], a[0][0], a[0][1], a[0][2], a[0][3], b0, b1);
                mma_tf32(acc[6 + nb], a[1][0], a[1][1], a[1][2], a[1][3], b0, b1);
            }
        }
    }

    #pragma unroll
    for (int mi = 0; mi < 2; mi++) {
        #pragma unroll
        for (int nb = 0; nb < 6; nb++) {
            #pragma unroll
            for (int half = 0; half < 2; half++) {
                int r = row0 + mw * 32 + mi * 16 + g + half * 8;
                int b_ = r >> 10, s = r & 1023;
                #pragma unroll
                for (int j = 0; j < 2; j++) {
                    int c = col0 + nw * 48 + nb * 8 + 2 * t + j;
                    int h = c >> 6, dh = c & 63;
                    out[(((size_t)(b_ * HH + h)) * SS + s) * DHH + dh] =
                        acc[mi * 6 + nb][half * 2 + j] + bias[c];
                }
            }
        }
    }
}

// ---------------- K2: fused scores + softmax + ctx (R10/R4 geometry) ----------------
// smem floats: S[32][1036] | Qs[32][68] | KV[2][128][68]
#define S_STR   1036
#define S_OFF   0
#define Q_OFF   (32 * S_STR)                 // 33152
#define KV_OFF  (Q_OFF + 32 * 68)            // 35328
#define KV_BUF  (128 * 68)                   // 8704
#define ATTN_SMEM_F (KV_OFF + 2 * KV_BUF)    // 52736
#define ATTN_SMEM_BYTES (ATTN_SMEM_F * 4)    // 210944

__global__ __launch_bounds__(512, 1) void attn_fused(
    const unsigned char* __restrict__ mask, float* __restrict__ attn)
{
    extern __shared__ float sm[];
    float* S   = sm + S_OFF;
    float* Qs  = sm + Q_OFF;
    float* KV  = sm + KV_OFF;

    const unsigned s_base = (unsigned)__cvta_generic_to_shared(sm);
    const unsigned q_base = s_base + Q_OFF * 4;
    const unsigned kv_base = s_base + KV_OFF * 4;

    const int bh = blockIdx.y;
    const int b_ = bh / HH, h = bh % HH;
    const int q0 = blockIdx.x * 32;
    const int tid = threadIdx.x;
    const int w = tid >> 5, lane = tid & 31, g = lane >> 2, t = lane & 3;

    // ldmatrix per-thread offsets
    const int a_row = (lane & 7) + ((lane >> 3) & 1) * 8;
    const int a_col = (lane >> 4) * 4;
    const int b_row = (lane & 7) + (lane >> 4) * 8;
    const int b_col = ((lane >> 3) & 1) * 4;

    const float* qp = g_q + ((size_t)bh * SS + q0) * DHH;
    const float* kp = g_k + (size_t)bh * SS * DHH;
    const float* vp = g_v + (size_t)bh * SS * DHH;

    // load Q tile to smem
    {
        int r = tid >> 4, c4 = (tid & 15) * 4;
        *(float4*)&Qs[r * 68 + c4] = *(const float4*)&qp[(size_t)r * 64 + c4];
    }

    #define KV_ISSUE(srcp, kc, buf)                                             \
        {                                                                       \
            const float* _sp = (srcp) + (size_t)(kc) * 64;                      \
            unsigned _db = kv_base + (buf) * (KV_BUF * 4);                      \
            _Pragma("unroll")                                                   \
            for (int _j = 0; _j < 4; _j++) {                                    \
                int _ch = tid + _j * 512;                                       \
                int _r = _ch >> 4, _c = (_ch & 15) * 4;                         \
                CP_ASYNC16(_db + (_r * 68 + _c) * 4, _sp + _r * 64 + _c);       \
            }                                                                   \
            CP_COMMIT();                                                        \
        }

    // ---- scores ----
    {
        const int mw = w & 1, nw = w >> 1;
        KV_ISSUE(kp, 0, 0);
        __syncthreads();

        unsigned qf[8][4];
        {
            unsigned qa = q_base + ((mw * 16 + a_row) * 68 + a_col) * 4;
            #pragma unroll
            for (int kk = 0; kk < 8; kk++)
                ldsm4(qf[kk][0], qf[kk][1], qf[kk][2], qf[kk][3], qa + kk * 32);
        }

        const unsigned kb_off = ((nw * 16 + b_row) * 68 + b_col) * 4;

        for (int c = 0; c < 8; c++) {
            if (c < 7) KV_ISSUE(kp, (c + 1) * 128, (c + 1) & 1);
            if (c < 7) { CP_WAIT1(); } else { CP_WAIT0(); }
            __syncthreads();
            const unsigned kb = kv_base + (c & 1) * (KV_BUF * 4) + kb_off;
            float acc[2][4] = {};
            #pragma unroll
            for (int kk = 0; kk < 8; kk++) {
                unsigned b0, b1, b2, b3;
                ldsm4(b0, b1, b2, b3, kb + kk * 32);
                mma_tf32(acc[0], qf[kk][0], qf[kk][1], qf[kk][2], qf[kk][3], b0, b1);
                mma_tf32(acc[1], qf[kk][0], qf[kk][1], qf[kk][2], qf[kk][3], b2, b3);
            }
            int m = mw * 16 + g;
            #pragma unroll
            for (int nb = 0; nb < 2; nb++) {
                int cc = c * 128 + nw * 16 + nb * 8 + 2 * t;
                *(float2*)&S[m * S_STR + cc] =
                    make_float2(acc[nb][0] * INV_SCALE, acc[nb][1] * INV_SCALE);
                *(float2*)&S[(m + 8) * S_STR + cc] =
                    make_float2(acc[nb][2] * INV_SCALE, acc[nb][3] * INV_SCALE);
            }
            __syncthreads();
        }
    }

    // prefetch V chunk 0 under the softmax
    KV_ISSUE(vp, 0, 0);

    // ---- softmax ----
    {
        #pragma unroll
        for (int rr = 0; rr < 2; rr++) {
            int r = w * 2 + rr;
            float* srow = S + r * S_STR;
            const unsigned* mrow =
                (const unsigned*)(mask + ((size_t)b_ * SS + q0 + r) * SS);
            float4 v[8];
            float mx = -1e30f;
            #pragma unroll
            for (int i = 0; i < 8; i++) {
                v[i] = *(float4*)&srow[i * 128 + lane * 4];
                unsigned mword = mrow[i * 32 + lane];
                if (mword & 0x000000ffu) v[i].x = -1e9f;
                if (mword & 0x0000ff00u) v[i].y = -1e9f;
                if (mword & 0x00ff0000u) v[i].z = -1e9f;
                if (mword & 0xff000000u) v[i].w = -1e9f;
                mx = fmaxf(mx, fmaxf(fmaxf(v[i].x, v[i].y), fmaxf(v[i].z, v[i].w)));
            }
            #pragma unroll
            for (int d = 16; d > 0; d >>= 1)
                mx = fmaxf(mx, __shfl_xor_sync(0xffffffffu, mx, d));
            float sum = 0.f;
            #pragma unroll
            for (int i = 0; i < 8; i++) {
                v[i].x = __expf(v[i].x - mx);
                v[i].y = __expf(v[i].y - mx);
                v[i].z = __expf(v[i].z - mx);
                v[i].w = __expf(v[i].w - mx);
                sum += v[i].x + v[i].y + v[i].z + v[i].w;
            }
            #pragma unroll
            for (int d = 16; d > 0; d >>= 1)
                sum += __shfl_xor_sync(0xffffffffu, sum, d);
            float rinv = 1.0f / sum;
            float* arow = attn + ((size_t)bh * SS + q0 + r) * SS;
            #pragma unroll
            for (int i = 0; i < 8; i++) {
                float4 p = make_float4(v[i].x * rinv, v[i].y * rinv,
                                       v[i].z * rinv, v[i].w * rinv);
                *(float4*)&srow[i * 128 + lane * 4] = p;
                *(float4*)&arow[i * 128 + lane * 4] = p;
            }
        }
    }

    // ---- ctx ----
    {
        const int mw = w & 1;
        const int n0 = (w >> 1) * 8;
        const unsigned sa_off = ((mw * 16 + a_row) * S_STR + a_col) * 4;
        float acc[4] = {};
        for (int c = 0; c < 8; c++) {
            if (c < 7) KV_ISSUE(vp, (c + 1) * 128, (c + 1) & 1);
            if (c < 7) { CP_WAIT1(); } else { CP_WAIT0(); }
            __syncthreads();
            const float* vb = KV + (c & 1) * KV_BUF;
            const int kc = c * 128;
            const unsigned sa = s_base + sa_off + kc * 4;
            #pragma unroll
            for (int kk = 0; kk < 16; kk++) {
                unsigned a0, a1, a2, a3;
                ldsm4(a0, a1, a2, a3, sa + kk * 32);
                unsigned b0 = __float_as_uint(vb[(kk * 8 + t) * 68 + n0 + g]);
                unsigned b1 = __float_as_uint(vb[(kk * 8 + t + 4) * 68 + n0 + g]);
                mma_tf32(acc, a0, a1, a2, a3, b0, b1);
            }
            __syncthreads();
        }
        int m = mw * 16 + g;
        int n = n0 + 2 * t;
        size_t base = ((size_t)(b_ * SS + q0 + m)) * HD + h * DHH + n;
        *(float2*)&g_ctx[base] = make_float2(acc[0], acc[1]);
        size_t base2 = ((size_t)(b_ * SS + q0 + m + 8)) * HD + h * DHH + n;
        *(float2*)&g_ctx[base2] = make_float2(acc[2], acc[3]);
    }
}

// ---------------- K3: out-proj (tf32 mma) + bias + residual -> g_x ----------------
__global__ __launch_bounds__(256) void oproj_mma(
    const float* __restrict__ Wo, const float* __restrict__ bo,
    const float* __restrict__ Qin)
{
    __shared__ float As[64 * 36];
    __shared__ float Bs[32 * 68];

    const int tid = threadIdx.x;
    const int w = tid >> 5, lane = tid & 31, g = lane >> 2, t = lane & 3;
    const int mb = w & 3, nh = w >> 2;
    const int row0 = blockIdx.y * 64;
    const int col0 = blockIdx.x * 64;

    float acc[4][4] = {};

    for (int k0 = 0; k0 < HD; k0 += 32) {
        __syncthreads();
        #pragma unroll
        for (int j = 0; j < 2; j++) {
            int f = tid + j * 256;
            int r = f >> 3, c4 = (f & 7) * 4;
            *(float4*)&As[r * 36 + c4] = *(const float4*)&g_ctx[(size_t)(row0 + r) * HD + k0 + c4];
        }
        #pragma unroll
        for (int j = 0; j < 2; j++) {
            int f = tid + j * 256;
            int r = f >> 4, c4 = (f & 15) * 4;
            *(float4*)&Bs[r * 68 + c4] = *(const float4*)&Wo[(size_t)(k0 + r) * DD + col0 + c4];
        }
        __syncthreads();
        #pragma unroll
        for (int kk = 0; kk < 4; kk++) {
            const float* ap = As + (mb * 16 + g) * 36 + kk * 8 + t;
            unsigned a0 = __float_as_uint(ap[0]);
            unsigned a1 = __float_as_uint(ap[8 * 36]);
            unsigned a2 = __float_as_uint(ap[4]);
            unsigned a3 = __float_as_uint(ap[8 * 36 + 4]);
            #pragma unroll
            for (int nb = 0; nb < 4; nb++) {
                int nc = nh * 32 + nb * 8 + g;
                unsigned b0 = __float_as_uint(Bs[(kk * 8 + t) * 68 + nc]);
                unsigned b1 = __float_as_uint(Bs[(kk * 8 + t + 4) * 68 + nc]);
                mma_tf32(acc[nb], a0, a1, a2, a3, b0, b1);
            }
        }
    }

    #pragma unroll
    for (int nb = 0; nb < 4; nb++) {
        #pragma unroll
        for (int half = 0; half < 2; half++) {
            int r = row0 + mb * 16 + g + half * 8;
            #pragma unroll
            for (int j = 0; j < 2; j++) {
                int c = col0 + nh * 32 + nb * 8 + 2 * t + j;
                g_x[(size_t)r * DD + c] =
                    acc[nb][half * 2 + j] + bo[c] + Qin[(size_t)r * DD + c];
            }
        }
    }
}

// ---------------- K4: LayerNorm + residual copy (float4) ----------------
__global__ __launch_bounds__(128) void ln_kernel(
    const float* __restrict__ Qin,
    const float* __restrict__ gamma, const float* __restrict__ beta,
    float* __restrict__ y, float* __restrict__ resid)
{
    const int r = blockIdx.x;
    const int t = threadIdx.x;
    const int w = t >> 5, lane = t & 31;
    __shared__ float red[4];

    const float4 xv = *(const float4*)&g_x[(size_t)r * DD + t * 4];

    float s = xv.x + xv.y + xv.z + xv.w;
    #pragma unroll
    for (int d = 16; d > 0; d >>= 1) s += __shfl_xor_sync(0xffffffffu, s, d);
    if (lane == 0) red[w] = s;
    __syncthreads();
    float mu = (red[0] + red[1] + red[2] + red[3]) * (1.0f / DD);

    float4 dv = make_float4(xv.x - mu, xv.y - mu, xv.z - mu, xv.w - mu);
    float ss = dv.x * dv.x + dv.y * dv.y + dv.z * dv.z + dv.w * dv.w;
    #pragma unroll
    for (int d = 16; d > 0; d >>= 1) ss += __shfl_xor_sync(0xffffffffu, ss, d);
    __syncthreads();
    if (lane == 0) red[w] = ss;
    __syncthreads();
    float var = (red[0] + red[1] + red[2] + red[3]) * (1.0f / DD);
    float rstd = rsqrtf(var + LN_EPS);

    const float4 gv = *(const float4*)&gamma[t * 4];
    const float4 bv = *(const float4*)&beta[t * 4];
    float4 yv = make_float4(dv.x * rstd * gv.x + bv.x,
                            dv.y * rstd * gv.y + bv.y,
                            dv.z * rstd * gv.z + bv.z,
                            dv.w * rstd * gv.w + bv.w);
    *(float4*)&y[(size_t)r * DD + t * 4] = yv;
    *(float4*)&resid[(size_t)r * DD + t * 4] =
        *(const float4*)&Qin[(size_t)r * DD + t * 4];
}

// ---------------- launcher ----------------
extern "C" void kernel_launch(void* const* d_in, const int* in_sizes, int n_in,
                              void* d_out, int out_size)
{
    const float* Q  = (const float*)d_in[0];
    const float* K  = (const float*)d_in[1];
    const float* V  = (const float*)d_in[2];
    const unsigned char* mask = (const unsigned char*)d_in[3];
    const float* Wq = (const float*)d_in[4];
    const float* bq = (const float*)d_in[5];
    const float* Wk = (const float*)d_in[6];
    const float* bk = (const float*)d_in[7];
    const float* Wv = (const float*)d_in[8];
    const float* bv = (const float*)d_in[9];
    const float* Wo = (const float*)d_in[10];
    const float* bo = (const float*)d_in[11];
    const float* gamma = (const float*)d_in[12];
    const float* beta  = (const float*)d_in[13];

    float* y     = (float*)d_out;
    float* attn  = y + (size_t)BB * SS * DD;
    float* resid = attn + (size_t)BB * HH * SS * SS;

    static bool attr_set = false;
    if (!attr_set) {
        cudaFuncSetAttribute(attn_fused, cudaFuncAttributeMaxDynamicSharedMemorySize,
                             ATTN_SMEM_BYTES);
        attr_set = true;
    }

    qkv_mma<<<dim3(HD / QKV_N, (BB * SS) / 64, 3), 256>>>(Q, K, V, Wq, bq, Wk, bk, Wv, bv);
    // MEASUREMENT ROUND: attn launched twice (idempotent — identical outputs).
    // dur_us(R13) - dur_us(R10) = true attn_fused duration.
    attn_fused<<<dim3(SS / 32, BB * HH), 512, ATTN_SMEM_BYTES>>>(mask, attn);
    attn_fused<<<dim3(SS / 32, BB * HH), 512, ATTN_SMEM_BYTES>>>(mask, attn);
    oproj_mma<<<dim3(DD / 64, (BB * SS) / 64), 256>>>(Wo, bo, Q);
    ln_kernel<<<BB * SS, 128>>>(Q, gamma, beta, y, resid);
}

// round 14
// speedup vs baseline: 1.7588x; 1.7588x over previous
#include <cuda_runtime.h>
#include <math.h>

#define BB 8
#define SS 1024
#define DD 512
#define HH 9
#define DHH 64
#define HD (HH*DHH)          // 576
#define INV_SCALE 0.13258252147247766f   // 1/sqrt(512/9)
#define LN_EPS 1e-5f

// ---------------- scratch (no allocs allowed) ----------------
__device__ float g_q[BB*HH*SS*DHH];   // [BH, S, DH]
__device__ float g_k[BB*HH*SS*DHH];
__device__ float g_v[BB*HH*SS*DHH];
__device__ float g_ctx[BB*SS*HD];     // [B*S, H*DH]
__device__ float g_x[BB*SS*DD];       // pre-LN activations

// ---------------- mma helper (raw fp32 bits as tf32: RZ truncation) ----------------
__device__ __forceinline__ void mma_tf32(float c[4],
                                         unsigned a0, unsigned a1, unsigned a2, unsigned a3,
                                         unsigned b0, unsigned b1)
{
    asm volatile(
        "mma.sync.aligned.m16n8k8.row.col.f32.tf32.tf32.f32 "
        "{%0,%1,%2,%3}, {%4,%5,%6,%7}, {%8,%9}, {%0,%1,%2,%3};\n"
        : "+f"(c[0]), "+f"(c[1]), "+f"(c[2]), "+f"(c[3])
        : "r"(a0), "r"(a1), "r"(a2), "r"(a3), "r"(b0), "r"(b1));
}

__device__ __forceinline__ void ldsm4(unsigned& r0, unsigned& r1, unsigned& r2, unsigned& r3,
                                      unsigned addr)
{
    asm volatile("ldmatrix.sync.aligned.m8n8.x4.shared.b16 {%0,%1,%2,%3}, [%4];\n"
                 : "=r"(r0), "=r"(r1), "=r"(r2), "=r"(r3) : "r"(addr));
}

#define CP_ASYNC16(dst_u32, src_ptr) \
    asm volatile("cp.async.ca.shared.global [%0], [%1], 16;\n" :: "r"(dst_u32), "l"(src_ptr))
#define CP_COMMIT() asm volatile("cp.async.commit_group;\n" ::)
#define CP_WAIT1()  asm volatile("cp.async.wait_group 1;\n" ::)
#define CP_WAIT0()  asm volatile("cp.async.wait_group 0;\n" ::)

// ---------------- K1: QKV projection, 64x192 tiles, cp.async double-buffered ----------------
#define QKV_N 192
#define QKV_BSTR 196
#define QKV_A_F 2304                 // 64*36
#define QKV_B_F 6272                 // 32*196
#define QKV_SMEM_F (2*QKV_A_F + 2*QKV_B_F)   // 17152
#define QKV_SMEM_BYTES (QKV_SMEM_F * 4)      // 68608

__global__ __launch_bounds__(256) void qkv_mma(
    const float* __restrict__ Xq, const float* __restrict__ Xk, const float* __restrict__ Xv,
    const float* __restrict__ Wq, const float* __restrict__ bq,
    const float* __restrict__ Wk, const float* __restrict__ bk,
    const float* __restrict__ Wv, const float* __restrict__ bv)
{
    extern __shared__ float qsm[];
    const unsigned qsm_base = (unsigned)__cvta_generic_to_shared(qsm);

    const int which = blockIdx.z;
    const float* X = (which == 0) ? Xq : (which == 1) ? Xk : Xv;
    const float* W = (which == 0) ? Wq : (which == 1) ? Wk : Wv;
    const float* bias = (which == 0) ? bq : (which == 1) ? bk : bv;
    float* out = (which == 0) ? g_q : (which == 1) ? g_k : g_v;

    const int tid = threadIdx.x;
    const int w = tid >> 5, lane = tid & 31, g = lane >> 2, t = lane & 3;
    const int mw = w & 1;
    const int nw = w >> 1;
    const int row0 = blockIdx.y * 64;
    const int col0 = blockIdx.x * QKV_N;

    // issue loads for k-block k0 into buffer buf
    #define QKV_ISSUE(k0, buf)                                                     \
        {                                                                          \
            const float* _xa = X + (size_t)row0 * DD + (k0);                       \
            unsigned _da = qsm_base + (buf) * (QKV_A_F * 4);                       \
            _Pragma("unroll")                                                      \
            for (int _j = 0; _j < 2; _j++) {                                       \
                int _f = tid + _j * 256;                                           \
                int _r = _f >> 3, _c4 = (_f & 7) * 4;                              \
                CP_ASYNC16(_da + (_r * 36 + _c4) * 4, _xa + (size_t)_r * DD + _c4);\
            }                                                                      \
            const float* _wb = W + (size_t)(k0) * HD + col0;                       \
            unsigned _db = qsm_base + (2 * QKV_A_F + (buf) * QKV_B_F) * 4;         \
            _Pragma("unroll")                                                      \
            for (int _j = 0; _j < 6; _j++) {                                       \
                int _f = tid + _j * 256;                                           \
                int _r = _f / 48, _c4 = (_f % 48) * 4;                             \
                CP_ASYNC16(_db + (_r * QKV_BSTR + _c4) * 4,                        \
                           _wb + (size_t)_r * HD + _c4);                           \
            }                                                                      \
            CP_COMMIT();                                                           \
        }

    float acc[12][4] = {};

    QKV_ISSUE(0, 0);
    for (int c = 0; c < 16; c++) {
        if (c < 15) QKV_ISSUE((c + 1) * 32, (c + 1) & 1);
        if (c < 15) { CP_WAIT1(); } else { CP_WAIT0(); }
        __syncthreads();
        const float* As = qsm + (c & 1) * QKV_A_F;
        const float* Bs = qsm + 2 * QKV_A_F + (c & 1) * QKV_B_F;
        #pragma unroll
        for (int kk = 0; kk < 4; kk++) {
            unsigned a[2][4];
            #pragma unroll
            for (int mi = 0; mi < 2; mi++) {
                const float* ap = As + (mw * 32 + mi * 16 + g) * 36 + kk * 8 + t;
                a[mi][0] = __float_as_uint(ap[0]);
                a[mi][1] = __float_as_uint(ap[8 * 36]);
                a[mi][2] = __float_as_uint(ap[4]);
                a[mi][3] = __float_as_uint(ap[8 * 36 + 4]);
            }
            #pragma unroll
            for (int nb = 0; nb < 6; nb++) {
                int nc = nw * 48 + nb * 8 + g;
                unsigned b0 = __float_as_uint(Bs[(kk * 8 + t) * QKV_BSTR + nc]);
                unsigned b1 = __float_as_uint(Bs[(kk * 8 + t + 4) * QKV_BSTR + nc]);
                mma_tf32(acc[nb], a[0][0], a[0][1], a[0][2], a[0][3], b0, b1);
                mma_tf32(acc[6 + nb], a[1][0], a[1][1], a[1][2], a[1][3], b0, b1);
            }
        }
        __syncthreads();
    }

    #pragma unroll
    for (int mi = 0; mi < 2; mi++) {
        #pragma unroll
        for (int nb = 0; nb < 6; nb++) {
            #pragma unroll
            for (int half = 0; half < 2; half++) {
                int r = row0 + mw * 32 + mi * 16 + g + half * 8;
                int b_ = r >> 10, s = r & 1023;
                #pragma unroll
                for (int j = 0; j < 2; j++) {
                    int c = col0 + nw * 48 + nb * 8 + 2 * t + j;
                    int h = c >> 6, dh = c & 63;
                    out[(((size_t)(b_ * HH + h)) * SS + s) * DHH + dh] =
                        acc[mi * 6 + nb][half * 2 + j] + bias[c];
                }
            }
        }
    }
}

// ---------------- K2: fused scores + softmax + ctx (R10 exact, single launch) ----------------
// smem floats: S[32][1036] | Qs[32][68] | KV[2][128][68]
#define S_STR   1036
#define S_OFF   0
#define Q_OFF   (32 * S_STR)                 // 33152
#define KV_OFF  (Q_OFF + 32 * 68)            // 35328
#define KV_BUF  (128 * 68)                   // 8704
#define ATTN_SMEM_F (KV_OFF + 2 * KV_BUF)    // 52736
#define ATTN_SMEM_BYTES (ATTN_SMEM_F * 4)    // 210944

__global__ __launch_bounds__(512, 1) void attn_fused(
    const unsigned char* __restrict__ mask, float* __restrict__ attn)
{
    extern __shared__ float sm[];
    float* S   = sm + S_OFF;
    float* Qs  = sm + Q_OFF;
    float* KV  = sm + KV_OFF;

    const unsigned s_base = (unsigned)__cvta_generic_to_shared(sm);
    const unsigned q_base = s_base + Q_OFF * 4;
    const unsigned kv_base = s_base + KV_OFF * 4;

    const int bh = blockIdx.y;
    const int b_ = bh / HH, h = bh % HH;
    const int q0 = blockIdx.x * 32;
    const int tid = threadIdx.x;
    const int w = tid >> 5, lane = tid & 31, g = lane >> 2, t = lane & 3;

    const int a_row = (lane & 7) + ((lane >> 3) & 1) * 8;
    const int a_col = (lane >> 4) * 4;
    const int b_row = (lane & 7) + (lane >> 4) * 8;
    const int b_col = ((lane >> 3) & 1) * 4;

    const float* qp = g_q + ((size_t)bh * SS + q0) * DHH;
    const float* kp = g_k + (size_t)bh * SS * DHH;
    const float* vp = g_v + (size_t)bh * SS * DHH;

    {
        int r = tid >> 4, c4 = (tid & 15) * 4;
        *(float4*)&Qs[r * 68 + c4] = *(const float4*)&qp[(size_t)r * 64 + c4];
    }

    #define KV_ISSUE(srcp, kc, buf)                                             \
        {                                                                       \
            const float* _sp = (srcp) + (size_t)(kc) * 64;                      \
            unsigned _db = kv_base + (buf) * (KV_BUF * 4);                      \
            _Pragma("unroll")                                                   \
            for (int _j = 0; _j < 4; _j++) {                                    \
                int _ch = tid + _j * 512;                                       \
                int _r = _ch >> 4, _c = (_ch & 15) * 4;                         \
                CP_ASYNC16(_db + (_r * 68 + _c) * 4, _sp + _r * 64 + _c);       \
            }                                                                   \
            CP_COMMIT();                                                        \
        }

    // ---- scores ----
    {
        const int mw = w & 1, nw = w >> 1;
        KV_ISSUE(kp, 0, 0);
        __syncthreads();

        unsigned qf[8][4];
        {
            unsigned qa = q_base + ((mw * 16 + a_row) * 68 + a_col) * 4;
            #pragma unroll
            for (int kk = 0; kk < 8; kk++)
                ldsm4(qf[kk][0], qf[kk][1], qf[kk][2], qf[kk][3], qa + kk * 32);
        }

        const unsigned kb_off = ((nw * 16 + b_row) * 68 + b_col) * 4;

        for (int c = 0; c < 8; c++) {
            if (c < 7) KV_ISSUE(kp, (c + 1) * 128, (c + 1) & 1);
            if (c < 7) { CP_WAIT1(); } else { CP_WAIT0(); }
            __syncthreads();
            const unsigned kb = kv_base + (c & 1) * (KV_BUF * 4) + kb_off;
            float acc[2][4] = {};
            #pragma unroll
            for (int kk = 0; kk < 8; kk++) {
                unsigned b0, b1, b2, b3;
                ldsm4(b0, b1, b2, b3, kb + kk * 32);
                mma_tf32(acc[0], qf[kk][0], qf[kk][1], qf[kk][2], qf[kk][3], b0, b1);
                mma_tf32(acc[1], qf[kk][0], qf[kk][1], qf[kk][2], qf[kk][3], b2, b3);
            }
            int m = mw * 16 + g;
            #pragma unroll
            for (int nb = 0; nb < 2; nb++) {
                int cc = c * 128 + nw * 16 + nb * 8 + 2 * t;
                *(float2*)&S[m * S_STR + cc] =
                    make_float2(acc[nb][0] * INV_SCALE, acc[nb][1] * INV_SCALE);
                *(float2*)&S[(m + 8) * S_STR + cc] =
                    make_float2(acc[nb][2] * INV_SCALE, acc[nb][3] * INV_SCALE);
            }
            __syncthreads();
        }
    }

    // prefetch V chunk 0 under the softmax
    KV_ISSUE(vp, 0, 0);

    // ---- softmax ----
    {
        #pragma unroll
        for (int rr = 0; rr < 2; rr++) {
            int r = w * 2 + rr;
            float* srow = S + r * S_STR;
            const unsigned* mrow =
                (const unsigned*)(mask + ((size_t)b_ * SS + q0 + r) * SS);
            float4 v[8];
            float mx = -1e30f;
            #pragma unroll
            for (int i = 0; i < 8; i++) {
                v[i] = *(float4*)&srow[i * 128 + lane * 4];
                unsigned mword = mrow[i * 32 + lane];
                if (mword & 0x000000ffu) v[i].x = -1e9f;
                if (mword & 0x0000ff00u) v[i].y = -1e9f;
                if (mword & 0x00ff0000u) v[i].z = -1e9f;
                if (mword & 0xff000000u) v[i].w = -1e9f;
                mx = fmaxf(mx, fmaxf(fmaxf(v[i].x, v[i].y), fmaxf(v[i].z, v[i].w)));
            }
            #pragma unroll
            for (int d = 16; d > 0; d >>= 1)
                mx = fmaxf(mx, __shfl_xor_sync(0xffffffffu, mx, d));
            float sum = 0.f;
            #pragma unroll
            for (int i = 0; i < 8; i++) {
                v[i].x = __expf(v[i].x - mx);
                v[i].y = __expf(v[i].y - mx);
                v[i].z = __expf(v[i].z - mx);
                v[i].w = __expf(v[i].w - mx);
                sum += v[i].x + v[i].y + v[i].z + v[i].w;
            }
            #pragma unroll
            for (int d = 16; d > 0; d >>= 1)
                sum += __shfl_xor_sync(0xffffffffu, sum, d);
            float rinv = 1.0f / sum;
            float* arow = attn + ((size_t)bh * SS + q0 + r) * SS;
            #pragma unroll
            for (int i = 0; i < 8; i++) {
                float4 p = make_float4(v[i].x * rinv, v[i].y * rinv,
                                       v[i].z * rinv, v[i].w * rinv);
                *(float4*)&srow[i * 128 + lane * 4] = p;
                *(float4*)&arow[i * 128 + lane * 4] = p;
            }
        }
    }

    // ---- ctx ----
    {
        const int mw = w & 1;
        const int n0 = (w >> 1) * 8;
        const unsigned sa_off = ((mw * 16 + a_row) * S_STR + a_col) * 4;
        float acc[4] = {};
        for (int c = 0; c < 8; c++) {
            if (c < 7) KV_ISSUE(vp, (c + 1) * 128, (c + 1) & 1);
            if (c < 7) { CP_WAIT1(); } else { CP_WAIT0(); }
            __syncthreads();
            const float* vb = KV + (c & 1) * KV_BUF;
            const int kc = c * 128;
            const unsigned sa = s_base + sa_off + kc * 4;
            #pragma unroll
            for (int kk = 0; kk < 16; kk++) {
                unsigned a0, a1, a2, a3;
                ldsm4(a0, a1, a2, a3, sa + kk * 32);
                unsigned b0 = __float_as_uint(vb[(kk * 8 + t) * 68 + n0 + g]);
                unsigned b1 = __float_as_uint(vb[(kk * 8 + t + 4) * 68 + n0 + g]);
                mma_tf32(acc, a0, a1, a2, a3, b0, b1);
            }
            __syncthreads();
        }
        int m = mw * 16 + g;
        int n = n0 + 2 * t;
        size_t base = ((size_t)(b_ * SS + q0 + m)) * HD + h * DHH + n;
        *(float2*)&g_ctx[base] = make_float2(acc[0], acc[1]);
        size_t base2 = ((size_t)(b_ * SS + q0 + m + 8)) * HD + h * DHH + n;
        *(float2*)&g_ctx[base2] = make_float2(acc[2], acc[3]);
    }
}

// ---------------- K3: out-proj, 64x64 tiles, cp.async double-buffered ----------------
#define OP_A_F 2304                  // 64*36
#define OP_B_F 2176                  // 32*68
__global__ __launch_bounds__(256) void oproj_mma(
    const float* __restrict__ Wo, const float* __restrict__ bo,
    const float* __restrict__ Qin)
{
    __shared__ float osm[2 * OP_A_F + 2 * OP_B_F];   // 35.8 KB
    const unsigned osm_base = (unsigned)__cvta_generic_to_shared(osm);

    const int tid = threadIdx.x;
    const int w = tid >> 5, lane = tid & 31, g = lane >> 2, t = lane & 3;
    const int mb = w & 3, nh = w >> 2;
    const int row0 = blockIdx.y * 64;
    const int col0 = blockIdx.x * 64;

    #define OP_ISSUE(k0, buf)                                                       \
        {                                                                           \
            const float* _xa = g_ctx + (size_t)row0 * HD + (k0);                    \
            unsigned _da = osm_base + (buf) * (OP_A_F * 4);                         \
            _Pragma("unroll")                                                       \
            for (int _j = 0; _j < 2; _j++) {                                        \
                int _f = tid + _j * 256;                                            \
                int _r = _f >> 3, _c4 = (_f & 7) * 4;                               \
                CP_ASYNC16(_da + (_r * 36 + _c4) * 4, _xa + (size_t)_r * HD + _c4); \
            }                                                                       \
            const float* _wb = Wo + (size_t)(k0) * DD + col0;                       \
            unsigned _db = osm_base + (2 * OP_A_F + (buf) * OP_B_F) * 4;            \
            _Pragma("unroll")                                                       \
            for (int _j = 0; _j < 2; _j++) {                                        \
                int _f = tid + _j * 256;                                            \
                int _r = _f >> 4, _c4 = (_f & 15) * 4;                              \
                CP_ASYNC16(_db + (_r * 68 + _c4) * 4, _wb + (size_t)_r * DD + _c4); \
            }                                                                       \
            CP_COMMIT();                                                            \
        }

    float acc[4][4] = {};

    OP_ISSUE(0, 0);
    for (int c = 0; c < 18; c++) {
        if (c < 17) OP_ISSUE((c + 1) * 32, (c + 1) & 1);
        if (c < 17) { CP_WAIT1(); } else { CP_WAIT0(); }
        __syncthreads();
        const float* As = osm + (c & 1) * OP_A_F;
        const float* Bs = osm + 2 * OP_A_F + (c & 1) * OP_B_F;
        #pragma unroll
        for (int kk = 0; kk < 4; kk++) {
            const float* ap = As + (mb * 16 + g) * 36 + kk * 8 + t;
            unsigned a0 = __float_as_uint(ap[0]);
            unsigned a1 = __float_as_uint(ap[8 * 36]);
            unsigned a2 = __float_as_uint(ap[4]);
            unsigned a3 = __float_as_uint(ap[8 * 36 + 4]);
            #pragma unroll
            for (int nb = 0; nb < 4; nb++) {
                int nc = nh * 32 + nb * 8 + g;
                unsigned b0 = __float_as_uint(Bs[(kk * 8 + t) * 68 + nc]);
                unsigned b1 = __float_as_uint(Bs[(kk * 8 + t + 4) * 68 + nc]);
                mma_tf32(acc[nb], a0, a1, a2, a3, b0, b1);
            }
        }
        __syncthreads();
    }

    #pragma unroll
    for (int nb = 0; nb < 4; nb++) {
        #pragma unroll
        for (int half = 0; half < 2; half++) {
            int r = row0 + mb * 16 + g + half * 8;
            #pragma unroll
            for (int j = 0; j < 2; j++) {
                int c = col0 + nh * 32 + nb * 8 + 2 * t + j;
                g_x[(size_t)r * DD + c] =
                    acc[nb][half * 2 + j] + bo[c] + Qin[(size_t)r * DD + c];
            }
        }
    }
}

// ---------------- K4: LayerNorm + residual copy (float4) ----------------
__global__ __launch_bounds__(128) void ln_kernel(
    const float* __restrict__ Qin,
    const float* __restrict__ gamma, const float* __restrict__ beta,
    float* __restrict__ y, float* __restrict__ resid)
{
    const int r = blockIdx.x;
    const int t = threadIdx.x;
    const int w = t >> 5, lane = t & 31;
    __shared__ float red[4];

    const float4 xv = *(const float4*)&g_x[(size_t)r * DD + t * 4];

    float s = xv.x + xv.y + xv.z + xv.w;
    #pragma unroll
    for (int d = 16; d > 0; d >>= 1) s += __shfl_xor_sync(0xffffffffu, s, d);
    if (lane == 0) red[w] = s;
    __syncthreads();
    float mu = (red[0] + red[1] + red[2] + red[3]) * (1.0f / DD);

    float4 dv = make_float4(xv.x - mu, xv.y - mu, xv.z - mu, xv.w - mu);
    float ss = dv.x * dv.x + dv.y * dv.y + dv.z * dv.z + dv.w * dv.w;
    #pragma unroll
    for (int d = 16; d > 0; d >>= 1) ss += __shfl_xor_sync(0xffffffffu, ss, d);
    __syncthreads();
    if (lane == 0) red[w] = ss;
    __syncthreads();
    float var = (red[0] + red[1] + red[2] + red[3]) * (1.0f / DD);
    float rstd = rsqrtf(var + LN_EPS);

    const float4 gv = *(const float4*)&gamma[t * 4];
    const float4 bv = *(const float4*)&beta[t * 4];
    float4 yv = make_float4(dv.x * rstd * gv.x + bv.x,
                            dv.y * rstd * gv.y + bv.y,
                            dv.z * rstd * gv.z + bv.z,
                            dv.w * rstd * gv.w + bv.w);
    *(float4*)&y[(size_t)r * DD + t * 4] = yv;
    *(float4*)&resid[(size_t)r * DD + t * 4] =
        *(const float4*)&Qin[(size_t)r * DD + t * 4];
}

// ---------------- launcher ----------------
extern "C" void kernel_launch(void* const* d_in, const int* in_sizes, int n_in,
                              void* d_out, int out_size)
{
    const float* Q  = (const float*)d_in[0];
    const float* K  = (const float*)d_in[1];
    const float* V  = (const float*)d_in[2];
    const unsigned char* mask = (const unsigned char*)d_in[3];
    const float* Wq = (const float*)d_in[4];
    const float* bq = (const float*)d_in[5];
    const float* Wk = (const float*)d_in[6];
    const float* bk = (const float*)d_in[7];
    const float* Wv = (const float*)d_in[8];
    const float* bv = (const float*)d_in[9];
    const float* Wo = (const float*)d_in[10];
    const float* bo = (const float*)d_in[11];
    const float* gamma = (const float*)d_in[12];
    const float* beta  = (const float*)d_in[13];

    float* y     = (float*)d_out;
    float* attn  = y + (size_t)BB * SS * DD;
    float* resid = attn + (size_t)BB * HH * SS * SS;

    static bool attr_set = false;
    if (!attr_set) {
        cudaFuncSetAttribute(attn_fused, cudaFuncAttributeMaxDynamicSharedMemorySize,
                             ATTN_SMEM_BYTES);
        cudaFuncSetAttribute(qkv_mma, cudaFuncAttributeMaxDynamicSharedMemorySize,
                             QKV_SMEM_BYTES);
        attr_set = true;
    }

    qkv_mma<<<dim3(HD / QKV_N, (BB * SS) / 64, 3), 256, QKV_SMEM_BYTES>>>(
        Q, K, V, Wq, bq, Wk, bk, Wv, bv);
    attn_fused<<<dim3(SS / 32, BB * HH), 512, ATTN_SMEM_BYTES>>>(mask, attn);
    oproj_mma<<<dim3(DD / 64, (BB * SS) / 64), 256>>>(Wo, bo, Q);
    ln_kernel<<<BB * SS, 128>>>(Q, gamma, beta, y, resid);
}

// round 15
// speedup vs baseline: 1.9439x; 1.1053x over previous
#include <cuda_runtime.h>
#include <math.h>

#define BB 8
#define SS 1024
#define DD 512
#define HH 9
#define DHH 64
#define HD (HH*DHH)          // 576
#define INV_SCALE 0.13258252147247766f   // 1/sqrt(512/9)
#define LN_EPS 1e-5f

// ---------------- scratch (no allocs allowed) ----------------
__device__ float g_q[BB*HH*SS*DHH];   // [BH, S, DH]
__device__ float g_k[BB*HH*SS*DHH];   // [BH, S, DH]
__device__ float g_vT[BB*HH*DHH*SS];  // [BH, DH, S]  (transposed V)
__device__ float g_ctx[BB*SS*HD];     // [B*S, H*DH]
__device__ float g_x[BB*SS*DD];       // pre-LN activations
__device__ float g_wT[4*HD*DD];       // Wq^T,Wk^T,Wv^T [HD][DD]; Wo^T [DD][HD]

// ---------------- mma helper (raw fp32 bits as tf32: RZ truncation) ----------------
__device__ __forceinline__ void mma_tf32(float c[4],
                                         unsigned a0, unsigned a1, unsigned a2, unsigned a3,
                                         unsigned b0, unsigned b1)
{
    asm volatile(
        "mma.sync.aligned.m16n8k8.row.col.f32.tf32.tf32.f32 "
        "{%0,%1,%2,%3}, {%4,%5,%6,%7}, {%8,%9}, {%0,%1,%2,%3};\n"
        : "+f"(c[0]), "+f"(c[1]), "+f"(c[2]), "+f"(c[3])
        : "r"(a0), "r"(a1), "r"(a2), "r"(a3), "r"(b0), "r"(b1));
}

__device__ __forceinline__ void ldsm4(unsigned& r0, unsigned& r1, unsigned& r2, unsigned& r3,
                                      unsigned addr)
{
    asm volatile("ldmatrix.sync.aligned.m8n8.x4.shared.b16 {%0,%1,%2,%3}, [%4];\n"
                 : "=r"(r0), "=r"(r1), "=r"(r2), "=r"(r3) : "r"(addr));
}

__device__ __forceinline__ void ldsm2(unsigned& r0, unsigned& r1, unsigned addr)
{
    asm volatile("ldmatrix.sync.aligned.m8n8.x2.shared.b16 {%0,%1}, [%2];\n"
                 : "=r"(r0), "=r"(r1) : "r"(addr));
}

#define CP_ASYNC16(dst_u32, src_ptr) \
    asm volatile("cp.async.ca.shared.global [%0], [%1], 16;\n" :: "r"(dst_u32), "l"(src_ptr))
#define CP_COMMIT() asm volatile("cp.async.commit_group;\n" ::)
#define CP_WAIT1()  asm volatile("cp.async.wait_group 1;\n" ::)
#define CP_WAIT0()  asm volatile("cp.async.wait_group 0;\n" ::)

// ---------------- K0: weight transpose staging ----------------
__global__ __launch_bounds__(256) void transpose_w(
    const float* __restrict__ Wq, const float* __restrict__ Wk,
    const float* __restrict__ Wv, const float* __restrict__ Wo)
{
    __shared__ float tile[32][33];
    const int z = blockIdx.z;
    const float* src = (z == 0) ? Wq : (z == 1) ? Wk : (z == 2) ? Wv : Wo;
    const int R = (z < 3) ? DD : HD;   // src rows
    const int C = (z < 3) ? HD : DD;   // src cols
    float* dst = g_wT + (size_t)z * HD * DD;   // dst [C][R]

    const int c0 = blockIdx.x * 32, r0 = blockIdx.y * 32;
    if (c0 >= C || r0 >= R) return;

    for (int i = threadIdx.y; i < 32; i += 8) {
        tile[i][threadIdx.x] = src[(size_t)(r0 + i) * C + c0 + threadIdx.x];
    }
    __syncthreads();
    for (int i = threadIdx.y; i < 32; i += 8) {
        dst[(size_t)(c0 + i) * R + r0 + threadIdx.x] = tile[threadIdx.x][i];
    }
}

// ---------------- K1: QKV projection, 64x192 tiles, ldsm A+B, cp.async pipelined ----------------
#define QKV_N 192
#define QKV_A_F (64 * 36)            // 2304
#define QKV_B_F (192 * 36)           // 6912
#define QKV_SMEM_F (2*QKV_A_F + 2*QKV_B_F)   // 18432
#define QKV_SMEM_BYTES (QKV_SMEM_F * 4)      // 73728

__global__ __launch_bounds__(256) void qkv_mma(
    const float* __restrict__ Xq, const float* __restrict__ Xk, const float* __restrict__ Xv,
    const float* __restrict__ bq, const float* __restrict__ bk, const float* __restrict__ bv)
{
    extern __shared__ float qsm[];
    const unsigned qsm_base = (unsigned)__cvta_generic_to_shared(qsm);

    const int which = blockIdx.z;
    const float* X = (which == 0) ? Xq : (which == 1) ? Xk : Xv;
    const float* WT = g_wT + (size_t)which * HD * DD;   // [HD n][DD k]
    const float* bias = (which == 0) ? bq : (which == 1) ? bk : bv;

    const int tid = threadIdx.x;
    const int w = tid >> 5, lane = tid & 31, g = lane >> 2, t = lane & 3;
    const int mw = w & 1;
    const int nw = w >> 1;
    const int row0 = blockIdx.y * 64;
    const int col0 = blockIdx.x * QKV_N;

    // ldsm offsets
    const int a_row = (lane & 7) + ((lane >> 3) & 1) * 8;
    const int a_col = (lane >> 4) * 4;
    const int b_row = (lane & 7) + (lane >> 4) * 8;
    const int b_col = ((lane >> 3) & 1) * 4;

    #define QKV_ISSUE(k0, buf)                                                     \
        {                                                                          \
            const float* _xa = X + (size_t)row0 * DD + (k0);                       \
            unsigned _da = qsm_base + (buf) * (QKV_A_F * 4);                       \
            _Pragma("unroll")                                                      \
            for (int _j = 0; _j < 2; _j++) {                                       \
                int _f = tid + _j * 256;                                           \
                int _r = _f >> 3, _c4 = (_f & 7) * 4;                              \
                CP_ASYNC16(_da + (_r * 36 + _c4) * 4, _xa + (size_t)_r * DD + _c4);\
            }                                                                      \
            const float* _wb = WT + (size_t)col0 * DD + (k0);                      \
            unsigned _db = qsm_base + (2 * QKV_A_F + (buf) * QKV_B_F) * 4;         \
            _Pragma("unroll")                                                      \
            for (int _j = 0; _j < 6; _j++) {                                       \
                int _f = tid + _j * 256;                                           \
                int _r = _f >> 3, _c4 = (_f & 7) * 4;                              \
                CP_ASYNC16(_db + (_r * 36 + _c4) * 4,                              \
                           _wb + (size_t)_r * DD + _c4);                           \
            }                                                                      \
            CP_COMMIT();                                                           \
        }

    float acc[12][4] = {};

    QKV_ISSUE(0, 0);
    for (int c = 0; c < 16; c++) {
        if (c < 15) QKV_ISSUE((c + 1) * 32, (c + 1) & 1);
        if (c < 15) { CP_WAIT1(); } else { CP_WAIT0(); }
        __syncthreads();
        const unsigned As = qsm_base + (c & 1) * (QKV_A_F * 4);
        const unsigned Bs = qsm_base + (2 * QKV_A_F + (c & 1) * QKV_B_F) * 4;
        const unsigned a_off = As + ((mw * 32 + a_row) * 36 + a_col) * 4;
        const unsigned b_off = Bs + ((nw * 48 + b_row) * 36 + b_col) * 4;
        #pragma unroll
        for (int kk = 0; kk < 4; kk++) {
            unsigned a[2][4];
            #pragma unroll
            for (int mi = 0; mi < 2; mi++)
                ldsm4(a[mi][0], a[mi][1], a[mi][2], a[mi][3],
                      a_off + (mi * 16 * 36 + kk * 8) * 4);
            #pragma unroll
            for (int nb16 = 0; nb16 < 3; nb16++) {
                unsigned b0, b1, b2, b3;
                ldsm4(b0, b1, b2, b3, b_off + (nb16 * 16 * 36 + kk * 8) * 4);
                mma_tf32(acc[nb16 * 2 + 0], a[0][0], a[0][1], a[0][2], a[0][3], b0, b1);
                mma_tf32(acc[nb16 * 2 + 1], a[0][0], a[0][1], a[0][2], a[0][3], b2, b3);
                mma_tf32(acc[6 + nb16 * 2 + 0], a[1][0], a[1][1], a[1][2], a[1][3], b0, b1);
                mma_tf32(acc[6 + nb16 * 2 + 1], a[1][0], a[1][1], a[1][2], a[1][3], b2, b3);
            }
        }
        __syncthreads();
    }

    #pragma unroll
    for (int mi = 0; mi < 2; mi++) {
        #pragma unroll
        for (int nb = 0; nb < 6; nb++) {
            #pragma unroll
            for (int half = 0; half < 2; half++) {
                int r = row0 + mw * 32 + mi * 16 + g + half * 8;
                int b_ = r >> 10, s = r & 1023;
                #pragma unroll
                for (int j = 0; j < 2; j++) {
                    int c = col0 + nw * 48 + nb * 8 + 2 * t + j;
                    int h = c >> 6, dh = c & 63;
                    float val = acc[mi * 6 + nb][half * 2 + j] + bias[c];
                    if (which == 0)
                        g_q[(((size_t)(b_ * HH + h)) * SS + s) * DHH + dh] = val;
                    else if (which == 1)
                        g_k[(((size_t)(b_ * HH + h)) * SS + s) * DHH + dh] = val;
                    else
                        g_vT[(((size_t)(b_ * HH + h)) * DHH + dh) * SS + s] = val;
                }
            }
        }
    }
}

// ---------------- K2: fused scores + softmax + ctx (V^T ldsm B) ----------------
// smem floats: S[32][1036] | Qs[32][68] | KV[2][8704]
//   K phase: buf = [128 keys][68]  fp32
//   V phase: buf = [64 dh][132]    fp32 (8448 of 8704 used)
#define S_STR   1036
#define S_OFF   0
#define Q_OFF   (32 * S_STR)                 // 33152
#define KV_OFF  (Q_OFF + 32 * 68)            // 35328
#define KV_BUF  8704
#define ATTN_SMEM_F (KV_OFF + 2 * KV_BUF)    // 52736
#define ATTN_SMEM_BYTES (ATTN_SMEM_F * 4)    // 210944

__global__ __launch_bounds__(512, 1) void attn_fused(
    const unsigned char* __restrict__ mask, float* __restrict__ attn)
{
    extern __shared__ float sm[];
    float* S   = sm + S_OFF;
    float* Qs  = sm + Q_OFF;

    const unsigned s_base = (unsigned)__cvta_generic_to_shared(sm);
    const unsigned q_base = s_base + Q_OFF * 4;
    const unsigned kv_base = s_base + KV_OFF * 4;

    const int bh = blockIdx.y;
    const int b_ = bh / HH, h = bh % HH;
    const int q0 = blockIdx.x * 32;
    const int tid = threadIdx.x;
    const int w = tid >> 5, lane = tid & 31, g = lane >> 2, t = lane & 3;

    const int a_row = (lane & 7) + ((lane >> 3) & 1) * 8;
    const int a_col = (lane >> 4) * 4;
    const int b_row = (lane & 7) + (lane >> 4) * 8;
    const int b_col = ((lane >> 3) & 1) * 4;
    const int l15 = lane & 15;

    const float* qp = g_q + ((size_t)bh * SS + q0) * DHH;
    const float* kp = g_k + (size_t)bh * SS * DHH;
    const float* vTp = g_vT + (size_t)bh * DHH * SS;

    {
        int r = tid >> 4, c4 = (tid & 15) * 4;
        *(float4*)&Qs[r * 68 + c4] = *(const float4*)&qp[(size_t)r * 64 + c4];
    }

    // K loader: [128 keys][68] from [S,DH] rows
    #define K_ISSUE(kc, buf)                                                    \
        {                                                                       \
            const float* _sp = kp + (size_t)(kc) * 64;                          \
            unsigned _db = kv_base + (buf) * (KV_BUF * 4);                      \
            _Pragma("unroll")                                                   \
            for (int _j = 0; _j < 4; _j++) {                                    \
                int _ch = tid + _j * 512;                                       \
                int _r = _ch >> 4, _c = (_ch & 15) * 4;                         \
                CP_ASYNC16(_db + (_r * 68 + _c) * 4, _sp + _r * 64 + _c);       \
            }                                                                   \
            CP_COMMIT();                                                        \
        }

    // V^T loader: [64 dh][132] from [DH,S] rows, 128-seq chunk
    #define VT_ISSUE(kc, buf)                                                    \
        {                                                                        \
            const float* _sp = vTp + (size_t)(kc);                               \
            unsigned _db = kv_base + (buf) * (KV_BUF * 4);                       \
            _Pragma("unroll")                                                    \
            for (int _j = 0; _j < 4; _j++) {                                     \
                int _ch = tid + _j * 512;                                        \
                int _r = _ch >> 5, _c = (_ch & 31) * 4;                          \
                CP_ASYNC16(_db + (_r * 132 + _c) * 4, _sp + (size_t)_r * SS + _c); \
            }                                                                    \
            CP_COMMIT();                                                         \
        }

    // ---- scores ----
    {
        const int mw = w & 1, nw = w >> 1;
        K_ISSUE(0, 0);
        __syncthreads();

        unsigned qf[8][4];
        {
            unsigned qa = q_base + ((mw * 16 + a_row) * 68 + a_col) * 4;
            #pragma unroll
            for (int kk = 0; kk < 8; kk++)
                ldsm4(qf[kk][0], qf[kk][1], qf[kk][2], qf[kk][3], qa + kk * 32);
        }

        const unsigned kb_off = ((nw * 16 + b_row) * 68 + b_col) * 4;

        for (int c = 0; c < 8; c++) {
            if (c < 7) K_ISSUE((c + 1) * 128, (c + 1) & 1);
            if (c < 7) { CP_WAIT1(); } else { CP_WAIT0(); }
            __syncthreads();
            const unsigned kb = kv_base + (c & 1) * (KV_BUF * 4) + kb_off;
            float acc[2][4] = {};
            #pragma unroll
            for (int kk = 0; kk < 8; kk++) {
                unsigned b0, b1, b2, b3;
                ldsm4(b0, b1, b2, b3, kb + kk * 32);
                mma_tf32(acc[0], qf[kk][0], qf[kk][1], qf[kk][2], qf[kk][3], b0, b1);
                mma_tf32(acc[1], qf[kk][0], qf[kk][1], qf[kk][2], qf[kk][3], b2, b3);
            }
            int m = mw * 16 + g;
            #pragma unroll
            for (int nb = 0; nb < 2; nb++) {
                int cc = c * 128 + nw * 16 + nb * 8 + 2 * t;
                *(float2*)&S[m * S_STR + cc] =
                    make_float2(acc[nb][0] * INV_SCALE, acc[nb][1] * INV_SCALE);
                *(float2*)&S[(m + 8) * S_STR + cc] =
                    make_float2(acc[nb][2] * INV_SCALE, acc[nb][3] * INV_SCALE);
            }
            __syncthreads();
        }
    }

    // prefetch V^T chunk 0 under the softmax
    VT_ISSUE(0, 0);

    // ---- softmax ----
    {
        #pragma unroll
        for (int rr = 0; rr < 2; rr++) {
            int r = w * 2 + rr;
            float* srow = S + r * S_STR;
            const unsigned* mrow =
                (const unsigned*)(mask + ((size_t)b_ * SS + q0 + r) * SS);
            float4 v[8];
            float mx = -1e30f;
            #pragma unroll
            for (int i = 0; i < 8; i++) {
                v[i] = *(float4*)&srow[i * 128 + lane * 4];
                unsigned mword = mrow[i * 32 + lane];
                if (mword & 0x000000ffu) v[i].x = -1e9f;
                if (mword & 0x0000ff00u) v[i].y = -1e9f;
                if (mword & 0x00ff0000u) v[i].z = -1e9f;
                if (mword & 0xff000000u) v[i].w = -1e9f;
                mx = fmaxf(mx, fmaxf(fmaxf(v[i].x, v[i].y), fmaxf(v[i].z, v[i].w)));
            }
            #pragma unroll
            for (int d = 16; d > 0; d >>= 1)
                mx = fmaxf(mx, __shfl_xor_sync(0xffffffffu, mx, d));
            float sum = 0.f;
            #pragma unroll
            for (int i = 0; i < 8; i++) {
                v[i].x = __expf(v[i].x - mx);
                v[i].y = __expf(v[i].y - mx);
                v[i].z = __expf(v[i].z - mx);
                v[i].w = __expf(v[i].w - mx);
                sum += v[i].x + v[i].y + v[i].z + v[i].w;
            }
            #pragma unroll
            for (int d = 16; d > 0; d >>= 1)
                sum += __shfl_xor_sync(0xffffffffu, sum, d);
            float rinv = 1.0f / sum;
            float* arow = attn + ((size_t)bh * SS + q0 + r) * SS;
            #pragma unroll
            for (int i = 0; i < 8; i++) {
                float4 p = make_float4(v[i].x * rinv, v[i].y * rinv,
                                       v[i].z * rinv, v[i].w * rinv);
                *(float4*)&srow[i * 128 + lane * 4] = p;
                *(float4*)&arow[i * 128 + lane * 4] = p;
            }
        }
    }

    // ---- ctx: A = P (ldsm), B = V^T (ldsm.x2) ----
    {
        const int mw = w & 1;
        const int n0 = (w >> 1) * 8;
        const unsigned sa_off = ((mw * 16 + a_row) * S_STR + a_col) * 4;
        const unsigned vb_off = ((n0 + (l15 & 7)) * 132 + ((l15 >> 3) & 1) * 4) * 4;
        float acc[4] = {};
        for (int c = 0; c < 8; c++) {
            if (c < 7) VT_ISSUE((c + 1) * 128, (c + 1) & 1);
            if (c < 7) { CP_WAIT1(); } else { CP_WAIT0(); }
            __syncthreads();
            const unsigned vb = kv_base + (c & 1) * (KV_BUF * 4) + vb_off;
            const unsigned sa = s_base + sa_off + c * 128 * 4;
            #pragma unroll
            for (int kk = 0; kk < 16; kk++) {
                unsigned a0, a1, a2, a3;
                ldsm4(a0, a1, a2, a3, sa + kk * 32);
                unsigned b0, b1;
                ldsm2(b0, b1, vb + kk * 32);
                mma_tf32(acc, a0, a1, a2, a3, b0, b1);
            }
            __syncthreads();
        }
        int m = mw * 16 + g;
        int n = n0 + 2 * t;
        size_t base = ((size_t)(b_ * SS + q0 + m)) * HD + h * DHH + n;
        *(float2*)&g_ctx[base] = make_float2(acc[0], acc[1]);
        size_t base2 = ((size_t)(b_ * SS + q0 + m + 8)) * HD + h * DHH + n;
        *(float2*)&g_ctx[base2] = make_float2(acc[2], acc[3]);
    }
}

// ---------------- K3: out-proj, ldsm A+B from Wo^T, cp.async pipelined ----------------
#define OP_A_F (64 * 36)             // 2304
#define OP_B_F (64 * 36)             // 2304
__global__ __launch_bounds__(256) void oproj_mma(
    const float* __restrict__ bo, const float* __restrict__ Qin)
{
    __shared__ float osm[2 * OP_A_F + 2 * OP_B_F];   // 36.9 KB
    const unsigned osm_base = (unsigned)__cvta_generic_to_shared(osm);
    const float* WoT = g_wT + (size_t)3 * HD * DD;   // [DD n][HD k]

    const int tid = threadIdx.x;
    const int w = tid >> 5, lane = tid & 31, g = lane >> 2, t = lane & 3;
    const int mb = w & 3, nh = w >> 2;
    const int row0 = blockIdx.y * 64;
    const int col0 = blockIdx.x * 64;

    const int a_row = (lane & 7) + ((lane >> 3) & 1) * 8;
    const int a_col = (lane >> 4) * 4;
    const int b_row = (lane & 7) + (lane >> 4) * 8;
    const int b_col = ((lane >> 3) & 1) * 4;

    #define OP_ISSUE(k0, buf)                                                       \
        {                                                                           \
            const float* _xa = g_ctx + (size_t)row0 * HD + (k0);                    \
            unsigned _da = osm_base + (buf) * (OP_A_F * 4);                         \
            _Pragma("unroll")                                                       \
            for (int _j = 0; _j < 2; _j++) {                                        \
                int _f = tid + _j * 256;                                            \
                int _r = _f >> 3, _c4 = (_f & 7) * 4;                               \
                CP_ASYNC16(_da + (_r * 36 + _c4) * 4, _xa + (size_t)_r * HD + _c4); \
            }                                                                       \
            const float* _wb = WoT + (size_t)col0 * HD + (k0);                      \
            unsigned _db = osm_base + (2 * OP_A_F + (buf) * OP_B_F) * 4;            \
            _Pragma("unroll")                                                       \
            for (int _j = 0; _j < 2; _j++) {                                        \
                int _f = tid + _j * 256;                                            \
                int _r = _f >> 3, _c4 = (_f & 7) * 4;                               \
                CP_ASYNC16(_db + (_r * 36 + _c4) * 4, _wb + (size_t)_r * HD + _c4); \
            }                                                                       \
            CP_COMMIT();                                                            \
        }

    float acc[4][4] = {};

    OP_ISSUE(0, 0);
    for (int c = 0; c < 18; c++) {
        if (c < 17) OP_ISSUE((c + 1) * 32, (c + 1) & 1);
        if (c < 17) { CP_WAIT1(); } else { CP_WAIT0(); }
        __syncthreads();
        const unsigned As = osm_base + (c & 1) * (OP_A_F * 4);
        const unsigned Bs = osm_base + (2 * OP_A_F + (c & 1) * OP_B_F) * 4;
        const unsigned a_off = As + ((mb * 16 + a_row) * 36 + a_col) * 4;
        const unsigned b_off = Bs + ((nh * 32 + b_row) * 36 + b_col) * 4;
        #pragma unroll
        for (int kk = 0; kk < 4; kk++) {
            unsigned a0, a1, a2, a3;
            ldsm4(a0, a1, a2, a3, a_off + kk * 32);
            #pragma unroll
            for (int nb16 = 0; nb16 < 2; nb16++) {
                unsigned b0, b1, b2, b3;
                ldsm4(b0, b1, b2, b3, b_off + (nb16 * 16 * 36 + kk * 8) * 4);
                mma_tf32(acc[nb16 * 2 + 0], a0, a1, a2, a3, b0, b1);
                mma_tf32(acc[nb16 * 2 + 1], a0, a1, a2, a3, b2, b3);
            }
        }
        __syncthreads();
    }

    #pragma unroll
    for (int nb = 0; nb < 4; nb++) {
        #pragma unroll
        for (int half = 0; half < 2; half++) {
            int r = row0 + mb * 16 + g + half * 8;
            #pragma unroll
            for (int j = 0; j < 2; j++) {
                int c = col0 + nh * 32 + nb * 8 + 2 * t + j;
                g_x[(size_t)r * DD + c] =
                    acc[nb][half * 2 + j] + bo[c] + Qin[(size_t)r * DD + c];
            }
        }
    }
}

// ---------------- K4: LayerNorm + residual copy (float4) ----------------
__global__ __launch_bounds__(128) void ln_kernel(
    const float* __restrict__ Qin,
    const float* __restrict__ gamma, const float* __restrict__ beta,
    float* __restrict__ y, float* __restrict__ resid)
{
    const int r = blockIdx.x;
    const int t = threadIdx.x;
    const int w = t >> 5, lane = t & 31;
    __shared__ float red[4];

    const float4 xv = *(const float4*)&g_x[(size_t)r * DD + t * 4];

    float s = xv.x + xv.y + xv.z + xv.w;
    #pragma unroll
    for (int d = 16; d > 0; d >>= 1) s += __shfl_xor_sync(0xffffffffu, s, d);
    if (lane == 0) red[w] = s;
    __syncthreads();
    float mu = (red[0] + red[1] + red[2] + red[3]) * (1.0f / DD);

    float4 dv = make_float4(xv.x - mu, xv.y - mu, xv.z - mu, xv.w - mu);
    float ss = dv.x * dv.x + dv.y * dv.y + dv.z * dv.z + dv.w * dv.w;
    #pragma unroll
    for (int d = 16; d > 0; d >>= 1) ss += __shfl_xor_sync(0xffffffffu, ss, d);
    __syncthreads();
    if (lane == 0) red[w] = ss;
    __syncthreads();
    float var = (red[0] + red[1] + red[2] + red[3]) * (1.0f / DD);
    float rstd = rsqrtf(var + LN_EPS);

    const float4 gv = *(const float4*)&gamma[t * 4];
    const float4 bv = *(const float4*)&beta[t * 4];
    float4 yv = make_float4(dv.x * rstd * gv.x + bv.x,
                            dv.y * rstd * gv.y + bv.y,
                            dv.z * rstd * gv.z + bv.z,
                            dv.w * rstd * gv.w + bv.w);
    *(float4*)&y[(size_t)r * DD + t * 4] = yv;
    *(float4*)&resid[(size_t)r * DD + t * 4] =
        *(const float4*)&Qin[(size_t)r * DD + t * 4];
}

// ---------------- launcher ----------------
extern "C" void kernel_launch(void* const* d_in, const int* in_sizes, int n_in,
                              void* d_out, int out_size)
{
    const float* Q  = (const float*)d_in[0];
    const float* K  = (const float*)d_in[1];
    const float* V  = (const float*)d_in[2];
    const unsigned char* mask = (const unsigned char*)d_in[3];
    const float* Wq = (const float*)d_in[4];
    const float* bq = (const float*)d_in[5];
    const float* Wk = (const float*)d_in[6];
    const float* bk = (const float*)d_in[7];
    const float* Wv = (const float*)d_in[8];
    const float* bv = (const float*)d_in[9];
    const float* Wo = (const float*)d_in[10];
    const float* bo = (const float*)d_in[11];
    const float* gamma = (const float*)d_in[12];
    const float* beta  = (const float*)d_in[13];

    float* y     = (float*)d_out;
    float* attn  = y + (size_t)BB * SS * DD;
    float* resid = attn + (size_t)BB * HH * SS * SS;

    static bool attr_set = false;
    if (!attr_set) {
        cudaFuncSetAttribute(attn_fused, cudaFuncAttributeMaxDynamicSharedMemorySize,
                             ATTN_SMEM_BYTES);
        cudaFuncSetAttribute(qkv_mma, cudaFuncAttributeMaxDynamicSharedMemorySize,
                             QKV_SMEM_BYTES);
        attr_set = true;
    }

    transpose_w<<<dim3(18, 18, 4), dim3(32, 8)>>>(Wq, Wk, Wv, Wo);
    qkv_mma<<<dim3(HD / QKV_N, (BB * SS) / 64, 3), 256, QKV_SMEM_BYTES>>>(
        Q, K, V, bq, bk, bv);
    attn_fused<<<dim3(SS / 32, BB * HH), 512, ATTN_SMEM_BYTES>>>(mask, attn);
    oproj_mma<<<dim3(DD / 64, (BB * SS) / 64), 256>>>(bo, Q);
    ln_kernel<<<BB * SS, 128>>>(Q, gamma, beta, y, resid);
}

// round 16
// speedup vs baseline: 2.2146x; 1.1392x over previous
#include <cuda_runtime.h>
#include <cuda_bf16.h>
#include <math.h>

#define BB 8
#define SS 1024
#define DD 512
#define HH 9
#define DHH 64
#define HD (HH*DHH)          // 576
#define INV_SCALE 0.13258252147247766f   // 1/sqrt(512/9)
#define LN_EPS 1e-5f

// ---------------- scratch (no allocs allowed) ----------------
__device__ float g_q[BB*HH*SS*DHH];            // [BH, S, DH]
__device__ float g_k[BB*HH*SS*DHH];            // [BH, S, DH]
__device__ __nv_bfloat16 g_vT[BB*HH*DHH*SS];   // [BH, DH, S]  bf16 transposed V
__device__ float g_ctx[BB*SS*HD];              // [B*S, H*DH]
__device__ float g_x[BB*SS*DD];                // pre-LN activations
__device__ float g_wT[4*HD*DD];                // Wq^T,Wk^T,Wv^T [HD][DD]; Wo^T [DD][HD]

// ---------------- mma helpers ----------------
__device__ __forceinline__ void mma_tf32(float c[4],
                                         unsigned a0, unsigned a1, unsigned a2, unsigned a3,
                                         unsigned b0, unsigned b1)
{
    asm volatile(
        "mma.sync.aligned.m16n8k8.row.col.f32.tf32.tf32.f32 "
        "{%0,%1,%2,%3}, {%4,%5,%6,%7}, {%8,%9}, {%0,%1,%2,%3};\n"
        : "+f"(c[0]), "+f"(c[1]), "+f"(c[2]), "+f"(c[3])
        : "r"(a0), "r"(a1), "r"(a2), "r"(a3), "r"(b0), "r"(b1));
}

__device__ __forceinline__ void mma_bf16(float c[4],
                                         unsigned a0, unsigned a1, unsigned a2, unsigned a3,
                                         unsigned b0, unsigned b1)
{
    asm volatile(
        "mma.sync.aligned.m16n8k16.row.col.f32.bf16.bf16.f32 "
        "{%0,%1,%2,%3}, {%4,%5,%6,%7}, {%8,%9}, {%0,%1,%2,%3};\n"
        : "+f"(c[0]), "+f"(c[1]), "+f"(c[2]), "+f"(c[3])
        : "r"(a0), "r"(a1), "r"(a2), "r"(a3), "r"(b0), "r"(b1));
}

__device__ __forceinline__ void ldsm4(unsigned& r0, unsigned& r1, unsigned& r2, unsigned& r3,
                                      unsigned addr)
{
    asm volatile("ldmatrix.sync.aligned.m8n8.x4.shared.b16 {%0,%1,%2,%3}, [%4];\n"
                 : "=r"(r0), "=r"(r1), "=r"(r2), "=r"(r3) : "r"(addr));
}

__device__ __forceinline__ void ldsm2(unsigned& r0, unsigned& r1, unsigned addr)
{
    asm volatile("ldmatrix.sync.aligned.m8n8.x2.shared.b16 {%0,%1}, [%2];\n"
                 : "=r"(r0), "=r"(r1) : "r"(addr));
}

#define CP_ASYNC16(dst_u32, src_ptr) \
    asm volatile("cp.async.ca.shared.global [%0], [%1], 16;\n" :: "r"(dst_u32), "l"(src_ptr))
#define CP_COMMIT() asm volatile("cp.async.commit_group;\n" ::)
#define CP_WAIT1()  asm volatile("cp.async.wait_group 1;\n" ::)
#define CP_WAIT0()  asm volatile("cp.async.wait_group 0;\n" ::)

// ---------------- K0: weight transpose staging ----------------
__global__ __launch_bounds__(256) void transpose_w(
    const float* __restrict__ Wq, const float* __restrict__ Wk,
    const float* __restrict__ Wv, const float* __restrict__ Wo)
{
    __shared__ float tile[32][33];
    const int z = blockIdx.z;
    const float* src = (z == 0) ? Wq : (z == 1) ? Wk : (z == 2) ? Wv : Wo;
    const int R = (z < 3) ? DD : HD;
    const int C = (z < 3) ? HD : DD;
    float* dst = g_wT + (size_t)z * HD * DD;

    const int c0 = blockIdx.x * 32, r0 = blockIdx.y * 32;
    if (c0 >= C || r0 >= R) return;

    for (int i = threadIdx.y; i < 32; i += 8) {
        tile[i][threadIdx.x] = src[(size_t)(r0 + i) * C + c0 + threadIdx.x];
    }
    __syncthreads();
    for (int i = threadIdx.y; i < 32; i += 8) {
        dst[(size_t)(c0 + i) * R + r0 + threadIdx.x] = tile[threadIdx.x][i];
    }
}

// ---------------- K1: QKV projection, 64x192 tiles, ldsm A+B, cp.async pipelined ----------------
#define QKV_N 192
#define QKV_A_F (64 * 36)            // 2304
#define QKV_B_F (192 * 36)           // 6912
#define QKV_SMEM_F (2*QKV_A_F + 2*QKV_B_F)   // 18432
#define QKV_SMEM_BYTES (QKV_SMEM_F * 4)      // 73728

__global__ __launch_bounds__(256) void qkv_mma(
    const float* __restrict__ Xq, const float* __restrict__ Xk, const float* __restrict__ Xv,
    const float* __restrict__ bq, const float* __restrict__ bk, const float* __restrict__ bv)
{
    extern __shared__ float qsm[];
    const unsigned qsm_base = (unsigned)__cvta_generic_to_shared(qsm);

    const int which = blockIdx.z;
    const float* X = (which == 0) ? Xq : (which == 1) ? Xk : Xv;
    const float* WT = g_wT + (size_t)which * HD * DD;
    const float* bias = (which == 0) ? bq : (which == 1) ? bk : bv;

    const int tid = threadIdx.x;
    const int w = tid >> 5, lane = tid & 31, g = lane >> 2, t = lane & 3;
    const int mw = w & 1;
    const int nw = w >> 1;
    const int row0 = blockIdx.y * 64;
    const int col0 = blockIdx.x * QKV_N;

    const int a_row = (lane & 7) + ((lane >> 3) & 1) * 8;
    const int a_col = (lane >> 4) * 4;
    const int b_row = (lane & 7) + (lane >> 4) * 8;
    const int b_col = ((lane >> 3) & 1) * 4;

    #define QKV_ISSUE(k0, buf)                                                     \
        {                                                                          \
            const float* _xa = X + (size_t)row0 * DD + (k0);                       \
            unsigned _da = qsm_base + (buf) * (QKV_A_F * 4);                       \
            _Pragma("unroll")                                                      \
            for (int _j = 0; _j < 2; _j++) {                                       \
                int _f = tid + _j * 256;                                           \
                int _r = _f >> 3, _c4 = (_f & 7) * 4;                              \
                CP_ASYNC16(_da + (_r * 36 + _c4) * 4, _xa + (size_t)_r * DD + _c4);\
            }                                                                      \
            const float* _wb = WT + (size_t)col0 * DD + (k0);                      \
            unsigned _db = qsm_base + (2 * QKV_A_F + (buf) * QKV_B_F) * 4;         \
            _Pragma("unroll")                                                      \
            for (int _j = 0; _j < 6; _j++) {                                       \
                int _f = tid + _j * 256;                                           \
                int _r = _f >> 3, _c4 = (_f & 7) * 4;                              \
                CP_ASYNC16(_db + (_r * 36 + _c4) * 4,                              \
                           _wb + (size_t)_r * DD + _c4);                           \
            }                                                                      \
            CP_COMMIT();                                                           \
        }

    float acc[12][4] = {};

    QKV_ISSUE(0, 0);
    for (int c = 0; c < 16; c++) {
        if (c < 15) QKV_ISSUE((c + 1) * 32, (c + 1) & 1);
        if (c < 15) { CP_WAIT1(); } else { CP_WAIT0(); }
        __syncthreads();
        const unsigned As = qsm_base + (c & 1) * (QKV_A_F * 4);
        const unsigned Bs = qsm_base + (2 * QKV_A_F + (c & 1) * QKV_B_F) * 4;
        const unsigned a_off = As + ((mw * 32 + a_row) * 36 + a_col) * 4;
        const unsigned b_off = Bs + ((nw * 48 + b_row) * 36 + b_col) * 4;
        #pragma unroll
        for (int kk = 0; kk < 4; kk++) {
            unsigned a[2][4];
            #pragma unroll
            for (int mi = 0; mi < 2; mi++)
                ldsm4(a[mi][0], a[mi][1], a[mi][2], a[mi][3],
                      a_off + (mi * 16 * 36 + kk * 8) * 4);
            #pragma unroll
            for (int nb16 = 0; nb16 < 3; nb16++) {
                unsigned b0, b1, b2, b3;
                ldsm4(b0, b1, b2, b3, b_off + (nb16 * 16 * 36 + kk * 8) * 4);
                mma_tf32(acc[nb16 * 2 + 0], a[0][0], a[0][1], a[0][2], a[0][3], b0, b1);
                mma_tf32(acc[nb16 * 2 + 1], a[0][0], a[0][1], a[0][2], a[0][3], b2, b3);
                mma_tf32(acc[6 + nb16 * 2 + 0], a[1][0], a[1][1], a[1][2], a[1][3], b0, b1);
                mma_tf32(acc[6 + nb16 * 2 + 1], a[1][0], a[1][1], a[1][2], a[1][3], b2, b3);
            }
        }
        __syncthreads();
    }

    #pragma unroll
    for (int mi = 0; mi < 2; mi++) {
        #pragma unroll
        for (int nb = 0; nb < 6; nb++) {
            #pragma unroll
            for (int half = 0; half < 2; half++) {
                int r = row0 + mw * 32 + mi * 16 + g + half * 8;
                int b_ = r >> 10, s = r & 1023;
                #pragma unroll
                for (int j = 0; j < 2; j++) {
                    int c = col0 + nw * 48 + nb * 8 + 2 * t + j;
                    int h = c >> 6, dh = c & 63;
                    float val = acc[mi * 6 + nb][half * 2 + j] + bias[c];
                    if (which == 0)
                        g_q[(((size_t)(b_ * HH + h)) * SS + s) * DHH + dh] = val;
                    else if (which == 1)
                        g_k[(((size_t)(b_ * HH + h)) * SS + s) * DHH + dh] = val;
                    else
                        g_vT[(((size_t)(b_ * HH + h)) * DHH + dh) * SS + s] =
                            __float2bfloat16(val);
                }
            }
        }
    }
}

// ---------------- K2: fused scores + softmax + pack + ctx(bf16) ----------------
// smem floats: S[32][1036] fp32 (scores) -> repacked in place as bf16 [32][1032h]
//              Qs[32][68] | KV[2][8704 floats]
//   K phase: buf = [128 keys][68] fp32
//   V phase: buf = [64 dh][136] bf16 (17408 B of 34816 B used)
#define S_STR    1036
#define S16_STR  1032                 // halves
#define S_OFF    0
#define Q_OFF    (32 * S_STR)                 // 33152
#define KV_OFF   (Q_OFF + 32 * 68)            // 35328
#define KV_BUF   8704
#define ATTN_SMEM_F (KV_OFF + 2 * KV_BUF)     // 52736
#define ATTN_SMEM_BYTES (ATTN_SMEM_F * 4)     // 210944

__global__ __launch_bounds__(512, 1) void attn_fused(
    const unsigned char* __restrict__ mask, float* __restrict__ attn)
{
    extern __shared__ float sm[];
    float* S   = sm + S_OFF;
    float* Qs  = sm + Q_OFF;

    const unsigned s_base = (unsigned)__cvta_generic_to_shared(sm);
    const unsigned q_base = s_base + Q_OFF * 4;
    const unsigned kv_base = s_base + KV_OFF * 4;

    const int bh = blockIdx.y;
    const int b_ = bh / HH, h = bh % HH;
    const int q0 = blockIdx.x * 32;
    const int tid = threadIdx.x;
    const int w = tid >> 5, lane = tid & 31, g = lane >> 2, t = lane & 3;

    const int a_row = (lane & 7) + ((lane >> 3) & 1) * 8;
    const int a_col = (lane >> 4) * 4;
    const int b_row = (lane & 7) + (lane >> 4) * 8;
    const int b_col = ((lane >> 3) & 1) * 4;

    const float* qp = g_q + ((size_t)bh * SS + q0) * DHH;
    const float* kp = g_k + (size_t)bh * SS * DHH;
    const __nv_bfloat16* vTp = g_vT + (size_t)bh * DHH * SS;

    {
        int r = tid >> 4, c4 = (tid & 15) * 4;
        *(float4*)&Qs[r * 68 + c4] = *(const float4*)&qp[(size_t)r * 64 + c4];
    }

    // K loader: [128 keys][68] fp32
    #define K_ISSUE(kc, buf)                                                    \
        {                                                                       \
            const float* _sp = kp + (size_t)(kc) * 64;                          \
            unsigned _db = kv_base + (buf) * (KV_BUF * 4);                      \
            _Pragma("unroll")                                                   \
            for (int _j = 0; _j < 4; _j++) {                                    \
                int _ch = tid + _j * 512;                                       \
                int _r = _ch >> 4, _c = (_ch & 15) * 4;                         \
                CP_ASYNC16(_db + (_r * 68 + _c) * 4, _sp + _r * 64 + _c);       \
            }                                                                   \
            CP_COMMIT();                                                        \
        }

    // V^T bf16 loader: [64 dh][128 seq halves], stride 136 halves
    #define VT_ISSUE(kc, buf)                                                     \
        {                                                                         \
            const __nv_bfloat16* _sp = vTp + (size_t)(kc);                        \
            unsigned _db = kv_base + (buf) * (KV_BUF * 4);                        \
            _Pragma("unroll")                                                     \
            for (int _j = 0; _j < 2; _j++) {                                      \
                int _ch = tid + _j * 512;                                         \
                int _r = _ch >> 4, _c = (_ch & 15) * 8;                           \
                CP_ASYNC16(_db + (_r * 136 + _c) * 2, _sp + (size_t)_r * SS + _c);\
            }                                                                     \
            CP_COMMIT();                                                          \
        }

    // ---- scores (tf32, unchanged) ----
    {
        const int mw = w & 1, nw = w >> 1;
        K_ISSUE(0, 0);
        __syncthreads();

        unsigned qf[8][4];
        {
            unsigned qa = q_base + ((mw * 16 + a_row) * 68 + a_col) * 4;
            #pragma unroll
            for (int kk = 0; kk < 8; kk++)
                ldsm4(qf[kk][0], qf[kk][1], qf[kk][2], qf[kk][3], qa + kk * 32);
        }

        const unsigned kb_off = ((nw * 16 + b_row) * 68 + b_col) * 4;

        for (int c = 0; c < 8; c++) {
            if (c < 7) K_ISSUE((c + 1) * 128, (c + 1) & 1);
            if (c < 7) { CP_WAIT1(); } else { CP_WAIT0(); }
            __syncthreads();
            const unsigned kb = kv_base + (c & 1) * (KV_BUF * 4) + kb_off;
            float acc[2][4] = {};
            #pragma unroll
            for (int kk = 0; kk < 8; kk++) {
                unsigned b0, b1, b2, b3;
                ldsm4(b0, b1, b2, b3, kb + kk * 32);
                mma_tf32(acc[0], qf[kk][0], qf[kk][1], qf[kk][2], qf[kk][3], b0, b1);
                mma_tf32(acc[1], qf[kk][0], qf[kk][1], qf[kk][2], qf[kk][3], b2, b3);
            }
            int m = mw * 16 + g;
            #pragma unroll
            for (int nb = 0; nb < 2; nb++) {
                int cc = c * 128 + nw * 16 + nb * 8 + 2 * t;
                *(float2*)&S[m * S_STR + cc] =
                    make_float2(acc[nb][0] * INV_SCALE, acc[nb][1] * INV_SCALE);
                *(float2*)&S[(m + 8) * S_STR + cc] =
                    make_float2(acc[nb][2] * INV_SCALE, acc[nb][3] * INV_SCALE);
            }
            __syncthreads();
        }
    }

    // prefetch V^T chunk 0 (aliases dead K buffers; safe: scores loop ended with barrier)
    VT_ISSUE(0, 0);

    // ---- softmax (fp32, writes attn only) ----
    {
        #pragma unroll
        for (int rr = 0; rr < 2; rr++) {
            int r = w * 2 + rr;
            float* srow = S + r * S_STR;
            const unsigned* mrow =
                (const unsigned*)(mask + ((size_t)b_ * SS + q0 + r) * SS);
            float4 v[8];
            float mx = -1e30f;
            #pragma unroll
            for (int i = 0; i < 8; i++) {
                v[i] = *(float4*)&srow[i * 128 + lane * 4];
                unsigned mword = mrow[i * 32 + lane];
                if (mword & 0x000000ffu) v[i].x = -1e9f;
                if (mword & 0x0000ff00u) v[i].y = -1e9f;
                if (mword & 0x00ff0000u) v[i].z = -1e9f;
                if (mword & 0xff000000u) v[i].w = -1e9f;
                mx = fmaxf(mx, fmaxf(fmaxf(v[i].x, v[i].y), fmaxf(v[i].z, v[i].w)));
            }
            #pragma unroll
            for (int d = 16; d > 0; d >>= 1)
                mx = fmaxf(mx, __shfl_xor_sync(0xffffffffu, mx, d));
            float sum = 0.f;
            #pragma unroll
            for (int i = 0; i < 8; i++) {
                v[i].x = __expf(v[i].x - mx);
                v[i].y = __expf(v[i].y - mx);
                v[i].z = __expf(v[i].z - mx);
                v[i].w = __expf(v[i].w - mx);
                sum += v[i].x + v[i].y + v[i].z + v[i].w;
            }
            #pragma unroll
            for (int d = 16; d > 0; d >>= 1)
                sum += __shfl_xor_sync(0xffffffffu, sum, d);
            float rinv = 1.0f / sum;
            float* arow = attn + ((size_t)bh * SS + q0 + r) * SS;
            #pragma unroll
            for (int i = 0; i < 8; i++) {
                float4 p = make_float4(v[i].x * rinv, v[i].y * rinv,
                                       v[i].z * rinv, v[i].w * rinv);
                *(float4*)&arow[i * 128 + lane * 4] = p;
            }
        }
    }
    __syncthreads();   // attn writes visible block-wide; S fp32 no longer needed

    // ---- pack: read attn rows (L2) -> bf16 S16 in place over S ----
    {
        __nv_bfloat16* S16 = (__nv_bfloat16*)sm;
        const float* abase = attn + ((size_t)bh * SS + q0) * SS;
        #pragma unroll
        for (int j = 0; j < 16; j++) {
            int idx = tid + j * 512;
            int r = idx >> 8, c4 = (idx & 255) * 4;
            float4 p = *(const float4*)&abase[(size_t)r * SS + c4];
            __nv_bfloat162 lo = __floats2bfloat162_rn(p.x, p.y);
            __nv_bfloat162 hi = __floats2bfloat162_rn(p.z, p.w);
            *(__nv_bfloat162*)&S16[r * S16_STR + c4] = lo;
            *(__nv_bfloat162*)&S16[r * S16_STR + c4 + 2] = hi;
        }
    }
    __syncthreads();

    // ---- ctx (bf16 m16n8k16): C[32][64] = P @ V ----
    {
        const int mw = w & 1;
        const int n0 = (w >> 1) * 8;
        const unsigned sa_off = ((mw * 16 + (lane & 15)) * S16_STR + (lane >> 4) * 8) * 2;
        const unsigned vb_off = (((n0 + (lane & 7))) * 136 + ((lane >> 3) & 1) * 8) * 2;
        float acc[4] = {};
        for (int c = 0; c < 8; c++) {
            if (c < 7) VT_ISSUE((c + 1) * 128, (c + 1) & 1);
            if (c < 7) { CP_WAIT1(); } else { CP_WAIT0(); }
            __syncthreads();
            const unsigned vb = kv_base + (c & 1) * (KV_BUF * 4) + vb_off;
            const unsigned sa = s_base + sa_off + c * 128 * 2;
            #pragma unroll
            for (int kk = 0; kk < 8; kk++) {
                unsigned a0, a1, a2, a3;
                ldsm4(a0, a1, a2, a3, sa + kk * 32);
                unsigned b0, b1;
                ldsm2(b0, b1, vb + kk * 32);
                mma_bf16(acc, a0, a1, a2, a3, b0, b1);
            }
            __syncthreads();
        }
        int m = mw * 16 + g;
        int n = n0 + 2 * t;
        size_t base = ((size_t)(b_ * SS + q0 + m)) * HD + h * DHH + n;
        *(float2*)&g_ctx[base] = make_float2(acc[0], acc[1]);
        size_t base2 = ((size_t)(b_ * SS + q0 + m + 8)) * HD + h * DHH + n;
        *(float2*)&g_ctx[base2] = make_float2(acc[2], acc[3]);
    }
}

// ---------------- K3: out-proj, ldsm A+B from Wo^T, cp.async pipelined ----------------
#define OP_A_F (64 * 36)             // 2304
#define OP_B_F (64 * 36)             // 2304
__global__ __launch_bounds__(256) void oproj_mma(
    const float* __restrict__ bo, const float* __restrict__ Qin)
{
    __shared__ float osm[2 * OP_A_F + 2 * OP_B_F];
    const unsigned osm_base = (unsigned)__cvta_generic_to_shared(osm);
    const float* WoT = g_wT + (size_t)3 * HD * DD;

    const int tid = threadIdx.x;
    const int w = tid >> 5, lane = tid & 31, g = lane >> 2, t = lane & 3;
    const int mb = w & 3, nh = w >> 2;
    const int row0 = blockIdx.y * 64;
    const int col0 = blockIdx.x * 64;

    const int a_row = (lane & 7) + ((lane >> 3) & 1) * 8;
    const int a_col = (lane >> 4) * 4;
    const int b_row = (lane & 7) + (lane >> 4) * 8;
    const int b_col = ((lane >> 3) & 1) * 4;

    #define OP_ISSUE(k0, buf)                                                       \
        {                                                                           \
            const float* _xa = g_ctx + (size_t)row0 * HD + (k0);                    \
            unsigned _da = osm_base + (buf) * (OP_A_F * 4);                         \
            _Pragma("unroll")                                                       \
            for (int _j = 0; _j < 2; _j++) {                                        \
                int _f = tid + _j * 256;                                            \
                int _r = _f >> 3, _c4 = (_f & 7) * 4;                               \
                CP_ASYNC16(_da + (_r * 36 + _c4) * 4, _xa + (size_t)_r * HD + _c4); \
            }                                                                       \
            const float* _wb = WoT + (size_t)col0 * HD + (k0);                      \
            unsigned _db = osm_base + (2 * OP_A_F + (buf) * OP_B_F) * 4;            \
            _Pragma("unroll")                                                       \
            for (int _j = 0; _j < 2; _j++) {                                        \
                int _f = tid + _j * 256;                                            \
                int _r = _f >> 3, _c4 = (_f & 7) * 4;                               \
                CP_ASYNC16(_db + (_r * 36 + _c4) * 4, _wb + (size_t)_r * HD + _c4); \
            }                                                                       \
            CP_COMMIT();                                                            \
        }

    float acc[4][4] = {};

    OP_ISSUE(0, 0);
    for (int c = 0; c < 18; c++) {
        if (c < 17) OP_ISSUE((c + 1) * 32, (c + 1) & 1);
        if (c < 17) { CP_WAIT1(); } else { CP_WAIT0(); }
        __syncthreads();
        const unsigned As = osm_base + (c & 1) * (OP_A_F * 4);
        const unsigned Bs = osm_base + (2 * OP_A_F + (c & 1) * OP_B_F) * 4;
        const unsigned a_off = As + ((mb * 16 + a_row) * 36 + a_col) * 4;
        const unsigned b_off = Bs + ((nh * 32 + b_row) * 36 + b_col) * 4;
        #pragma unroll
        for (int kk = 0; kk < 4; kk++) {
            unsigned a0, a1, a2, a3;
            ldsm4(a0, a1, a2, a3, a_off + kk * 32);
            #pragma unroll
            for (int nb16 = 0; nb16 < 2; nb16++) {
                unsigned b0, b1, b2, b3;
                ldsm4(b0, b1, b2, b3, b_off + (nb16 * 16 * 36 + kk * 8) * 4);
                mma_tf32(acc[nb16 * 2 + 0], a0, a1, a2, a3, b0, b1);
                mma_tf32(acc[nb16 * 2 + 1], a0, a1, a2, a3, b2, b3);
            }
        }
        __syncthreads();
    }

    #pragma unroll
    for (int nb = 0; nb < 4; nb++) {
        #pragma unroll
        for (int half = 0; half < 2; half++) {
            int r = row0 + mb * 16 + g + half * 8;
            #pragma unroll
            for (int j = 0; j < 2; j++) {
                int c = col0 + nh * 32 + nb * 8 + 2 * t + j;
                g_x[(size_t)r * DD + c] =
                    acc[nb][half * 2 + j] + bo[c] + Qin[(size_t)r * DD + c];
            }
        }
    }
}

// ---------------- K4: LayerNorm + residual copy (float4) ----------------
__global__ __launch_bounds__(128) void ln_kernel(
    const float* __restrict__ Qin,
    const float* __restrict__ gamma, const float* __restrict__ beta,
    float* __restrict__ y, float* __restrict__ resid)
{
    const int r = blockIdx.x;
    const int t = threadIdx.x;
    const int w = t >> 5, lane = t & 31;
    __shared__ float red[4];

    const float4 xv = *(const float4*)&g_x[(size_t)r * DD + t * 4];

    float s = xv.x + xv.y + xv.z + xv.w;
    #pragma unroll
    for (int d = 16; d > 0; d >>= 1) s += __shfl_xor_sync(0xffffffffu, s, d);
    if (lane == 0) red[w] = s;
    __syncthreads();
    float mu = (red[0] + red[1] + red[2] + red[3]) * (1.0f / DD);

    float4 dv = make_float4(xv.x - mu, xv.y - mu, xv.z - mu, xv.w - mu);
    float ss = dv.x * dv.x + dv.y * dv.y + dv.z * dv.z + dv.w * dv.w;
    #pragma unroll
    for (int d = 16; d > 0; d >>= 1) ss += __shfl_xor_sync(0xffffffffu, ss, d);
    __syncthreads();
    if (lane == 0) red[w] = ss;
    __syncthreads();
    float var = (red[0] + red[1] + red[2] + red[3]) * (1.0f / DD);
    float rstd = rsqrtf(var + LN_EPS);

    const float4 gv = *(const float4*)&gamma[t * 4];
    const float4 bv = *(const float4*)&beta[t * 4];
    float4 yv = make_float4(dv.x * rstd * gv.x + bv.x,
                            dv.y * rstd * gv.y + bv.y,
                            dv.z * rstd * gv.z + bv.z,
                            dv.w * rstd * gv.w + bv.w);
    *(float4*)&y[(size_t)r * DD + t * 4] = yv;
    *(float4*)&resid[(size_t)r * DD + t * 4] =
        *(const float4*)&Qin[(size_t)r * DD + t * 4];
}

// ---------------- launcher ----------------
extern "C" void kernel_launch(void* const* d_in, const int* in_sizes, int n_in,
                              void* d_out, int out_size)
{
    const float* Q  = (const float*)d_in[0];
    const float* K  = (const float*)d_in[1];
    const float* V  = (const float*)d_in[2];
    const unsigned char* mask = (const unsigned char*)d_in[3];
    const float* Wq = (const float*)d_in[4];
    const float* bq = (const float*)d_in[5];
    const float* Wk = (const float*)d_in[6];
    const float* bk = (const float*)d_in[7];
    const float* Wv = (const float*)d_in[8];
    const float* bv = (const float*)d_in[9];
    const float* Wo = (const float*)d_in[10];
    const float* bo = (const float*)d_in[11];
    const float* gamma = (const float*)d_in[12];
    const float* beta  = (const float*)d_in[13];

    float* y     = (float*)d_out;
    float* attn  = y + (size_t)BB * SS * DD;
    float* resid = attn + (size_t)BB * HH * SS * SS;

    static bool attr_set = false;
    if (!attr_set) {
        cudaFuncSetAttribute(attn_fused, cudaFuncAttributeMaxDynamicSharedMemorySize,
                             ATTN_SMEM_BYTES);
        cudaFuncSetAttribute(qkv_mma, cudaFuncAttributeMaxDynamicSharedMemorySize,
                             QKV_SMEM_BYTES);
        attr_set = true;
    }

    transpose_w<<<dim3(18, 18, 4), dim3(32, 8)>>>(Wq, Wk, Wv, Wo);
    qkv_mma<<<dim3(HD / QKV_N, (BB * SS) / 64, 3), 256, QKV_SMEM_BYTES>>>(
        Q, K, V, bq, bk, bv);
    attn_fused<<<dim3(SS / 32, BB * HH), 512, ATTN_SMEM_BYTES>>>(mask, attn);
    oproj_mma<<<dim3(DD / 64, (BB * SS) / 64), 256>>>(bo, Q);
    ln_kernel<<<BB * SS, 128>>>(Q, gamma, beta, y, resid);
}